// round 4
// baseline (speedup 1.0000x reference)
#include <cuda_runtime.h>
#include <cstddef>
#include <cstdint>

#define NB 64
#define NT 1024
#define NV 256
#define NS 256
#define ND 24
#define NL 513          // 2*NS+1
#define DGA 1344        // allocated dg rows per batch (>= 1282 + prefetch slack)
#define GAMMA 0.1f
#define NEGF (-1e10f)
#define BIGF (1e10f)

// Scratch (no allocation allowed)
__device__ float g_pred[NB * NT * ND];            // predicted features (B,T,D)
__device__ float g_cost[(size_t)NB * DGA * NS];   // cost, layout [b][dg][j], dg=i+j+2 (0-based i,j)
__device__ float g_loss[2 * NB];                  // [0..63] ctc, [64..127] sdtw

// min <= md <= mx with pure min/max (no cancellation)
__device__ __forceinline__ void sort3(float a, float b, float c,
                                      float& mn, float& md, float& mx) {
    float t1 = fminf(a, b);
    float t2 = fmaxf(a, b);
    mn = fminf(t1, c);
    mx = fmaxf(t2, c);
    md = fmaxf(t1, fminf(t2, c));
}

__device__ __forceinline__ int acqLoad(int* p) {
    int v;
    asm volatile("ld.acquire.cta.shared.b32 %0, [%1];"
                 : "=r"(v) : "r"((uint32_t)__cvta_generic_to_shared(p)) : "memory");
    return v;
}
__device__ __forceinline__ void relStore(int* p, int v) {
    asm volatile("st.release.cta.shared.b32 [%0], %1;"
                 :: "r"((uint32_t)__cvta_generic_to_shared(p)), "r"(v) : "memory");
}

// ----------------------------------------------------------------------------
// Kernel 1: pred = exp(log_probs) @ fm   (65536 x 256) @ (256 x 24)
// Register-tiled: 256 threads, block tile = 128 rows x 24 dims, K chunked by 64.
// ----------------------------------------------------------------------------
__global__ __launch_bounds__(256) void prep_kernel(const float* __restrict__ lp,
                                                   const float* __restrict__ fm) {
    __shared__ float eS[64 * 129];
    __shared__ float fmS[64 * 25];

    const int tid = threadIdx.x;
    const int row0 = blockIdx.x * 128;
    const int rg = tid >> 3;       // 0..31 (row group of 4)
    const int dgrp = tid & 7;      // 0..7  (dim group of 3)

    float acc[4][3];
#pragma unroll
    for (int i = 0; i < 4; i++)
#pragma unroll
        for (int j = 0; j < 3; j++) acc[i][j] = 0.f;

    for (int v0 = 0; v0 < NV; v0 += 64) {
        for (int idx = tid; idx < 64 * 24; idx += 256) {
            int v = idx / 24, d = idx - v * 24;
            fmS[v * 25 + d] = fm[(v0 + v) * ND + d];
        }
        for (int idx = tid; idx < 128 * 64; idx += 256) {
            int r = idx >> 6, v = idx & 63;
            eS[v * 129 + r] = __expf(lp[(size_t)(row0 + r) * NV + v0 + v]);
        }
        __syncthreads();

#pragma unroll 4
        for (int v = 0; v < 64; v++) {
            float e0 = eS[v * 129 + rg * 4 + 0];
            float e1 = eS[v * 129 + rg * 4 + 1];
            float e2 = eS[v * 129 + rg * 4 + 2];
            float e3 = eS[v * 129 + rg * 4 + 3];
            float f0 = fmS[v * 25 + dgrp * 3 + 0];
            float f1 = fmS[v * 25 + dgrp * 3 + 1];
            float f2 = fmS[v * 25 + dgrp * 3 + 2];
            acc[0][0] += e0 * f0; acc[0][1] += e0 * f1; acc[0][2] += e0 * f2;
            acc[1][0] += e1 * f0; acc[1][1] += e1 * f1; acc[1][2] += e1 * f2;
            acc[2][0] += e2 * f0; acc[2][1] += e2 * f1; acc[2][2] += e2 * f2;
            acc[3][0] += e3 * f0; acc[3][1] += e3 * f1; acc[3][2] += e3 * f2;
        }
        __syncthreads();
    }

#pragma unroll
    for (int i = 0; i < 4; i++)
#pragma unroll
        for (int j = 0; j < 3; j++)
            g_pred[(size_t)(row0 + rg * 4 + i) * ND + dgrp * 3 + j] = acc[i][j];
}

// ----------------------------------------------------------------------------
// Kernel 2: sdtw cost matrix, layout [b][dg][j], dg = i+j+2.
// Block: 256 thr = 8 warps. i-tile = 64 rows (lane owns i0+lane, i0+lane+32),
// warp w covers j in [32w, 32w+32). Anti-diagonal rotation j = j0+((c-lane)&31)
// makes each warp-store hit <=2 consecutive dg rows (coalesced).
// ----------------------------------------------------------------------------
__global__ __launch_bounds__(256) void cost_kernel(const float* __restrict__ fm,
                                                   const int* __restrict__ targets) {
    __shared__ float predS[64 * 25];
    __shared__ float qS[256 * 25];
    __shared__ float pn[64];
    __shared__ float qn[256];
    __shared__ int qlab[256];

    const int tid = threadIdx.x;
    const int b = blockIdx.y;
    const int i0 = blockIdx.x * 64;

    if (tid < 256) qlab[tid] = targets[b * NS + tid];
    for (int idx = tid; idx < 64 * 24; idx += 256)
        predS[(idx / 24) * 25 + (idx % 24)] = g_pred[(size_t)(b * NT + i0) * ND + idx];
    __syncthreads();
    for (int idx = tid; idx < 256 * 24; idx += 256) {
        int c = idx / 24, d = idx - c * 24;
        qS[c * 25 + d] = fm[qlab[c] * ND + d];
    }
    __syncthreads();
    if (tid < 64) {
        float s = 0.f;
#pragma unroll
        for (int d = 0; d < ND; d++) { float x = predS[tid * 25 + d]; s += x * x; }
        pn[tid] = s;
    }
    {
        float s = 0.f;
#pragma unroll
        for (int d = 0; d < ND; d++) { float x = qS[tid * 25 + d]; s += x * x; }
        qn[tid] = s;
    }
    __syncthreads();

    const int w = tid >> 5;
    const int lane = tid & 31;
    const int j0 = w * 32;

    float p0[ND], p1[ND];
#pragma unroll
    for (int k = 0; k < ND; k++) {
        p0[k] = predS[lane * 25 + k];
        p1[k] = predS[(lane + 32) * 25 + k];
    }
    const float pn0 = pn[lane], pn1 = pn[lane + 32];
    const size_t cb = (size_t)b * DGA;
    const int D0 = i0 + j0 + 2;

#pragma unroll 4
    for (int c = 0; c < 32; c++) {
        int jc = j0 + ((c - lane) & 31);
        float dot0 = 0.f, dot1 = 0.f;
#pragma unroll
        for (int k = 0; k < ND; k++) {
            float q = qS[jc * 25 + k];
            dot0 += p0[k] * q;
            dot1 += p1[k] * q;
        }
        float qnj = qn[jc];
        int dg0 = D0 + c + ((lane > c) ? 32 : 0);
        g_cost[(cb + dg0) * NS + jc] = pn0 + qnj - 2.f * dot0;
        g_cost[(cb + dg0 + 32) * NS + jc] = pn1 + qnj - 2.f * dot1;
    }
}

// ----------------------------------------------------------------------------
// Kernel 3 (fused DP, barrier-free skewed-warp pipelines):
//   blocks 0..63  -> soft-DTW (8 active warps, skew 32 diags/warp)
//   blocks 64..127-> CTC forward (17 warps, skew 1 step/warp)
// Cross-warp boundaries through smem full-history arrays + release/acquire
// progress flags. No __syncthreads in the serial loops.
// ----------------------------------------------------------------------------
#define BNDW 1296
extern __shared__ char smdyn[];

__global__ __launch_bounds__(544) void main_kernel(const float* __restrict__ lp,
                                                   const int* __restrict__ targets,
                                                   const int* __restrict__ in_len,
                                                   const int* __restrict__ tg_len) {
    const int tid = threadIdx.x;
    const int lane = tid & 31;
    const int w = tid >> 5;
    const int bid = blockIdx.x;

    if (bid < NB) {
        // ======================= soft-DTW =======================
        float* bndR = (float*)smdyn;                 // [8][BNDW]
        int* progS = (int*)(smdyn + 8 * BNDW * 4);   // [8]
        const int b = bid;

        if (tid < 8) progS[tid] = 0;
        __syncthreads();
        if (tid >= 256) return;                      // warps 8..16 idle

        const int jj = tid + 1;                      // column 1..256
        const int s0 = 32 * w + 2;                   // first diagonal for this warp
        const int colLim = 32 * w + 1024;            // poll gate for lane0
        const float* cb = g_cost + (size_t)b * DGA * NS + tid;

        float Rp = BIGF;                             // R[dg-1][jj]
        float r3c = (tid == 0) ? 0.f : BIGF;         // carries R[dg-2][jj-1]
        int cached = 0;

        float cA[4], cB[4];
#pragma unroll
        for (int k = 0; k < 4; k++) {
            cA[k] = cb[(size_t)(s0 + k) * NS];
            cB[k] = cb[(size_t)(s0 + 4 + k) * NS];
        }

        for (int st = 0; st < 1056; st += 4) {
            float cC[4];
#pragma unroll
            for (int k = 0; k < 4; k++)
                cC[k] = cb[(size_t)(s0 + st + 8 + k) * NS];
#pragma unroll
            for (int k = 0; k < 4; k++) {
                const int dg = s0 + st + k;
                float r2 = __shfl_up_sync(0xffffffffu, Rp, 1);
                if (lane == 0) {
                    int need = dg - 1;
                    if (w == 0 || need > colLim) r2 = BIGF;
                    else {
                        while (cached < need) cached = acqLoad(&progS[w - 1]);
                        r2 = bndR[(w - 1) * BNDW + need];
                    }
                }
                float r1 = Rp, r3 = r3c;
                float mn, md, mx;
                sort3(r1, r2, r3, mn, md, mx);
                float s = 1.f + __expf((mn - md) * (1.f / GAMMA))
                              + __expf((mn - mx) * (1.f / GAMMA));
                const int i = dg - jj;
                float Rc = (i >= 1 && i <= NT) ? (cA[k] + mn - GAMMA * __logf(s)) : BIGF;
                if (lane == 31) { bndR[w * BNDW + dg] = Rc; relStore(&progS[w], dg); }
                if (tid == NS - 1 && dg == NT + NS) g_loss[NB + b] = Rc;
                r3c = r2;
                Rp = Rc;
            }
#pragma unroll
            for (int k = 0; k < 4; k++) { cA[k] = cB[k]; cB[k] = cC[k]; }
        }
    } else {
        // ======================= CTC forward =======================
        float* a30s = (float*)smdyn;                        // [17][1024]
        float* a31s = a30s + 17 * 1024;                     // [17][1024]
        int* progC = (int*)(a31s + 17 * 1024);              // [17] (padded)
        float* actc = (float*)(smdyn + 2 * 17 * 1024 * 4 + 128);  // [513]
        const int b = bid - NB;

        const int sC = (tid <= 512) ? tid : 512;
        int ext = 0;
        bool skip = false;
        if (sC & 1) {
            int kk = (sC - 1) >> 1;
            ext = targets[b * NS + kk];
            if (sC >= 3) skip = (ext != targets[b * NS + kk - 1]);
        }
        const float* lpb = lp + (size_t)b * NT * NV;

        // t = 0
        float A = (tid < 2) ? __ldg(lpb + ext) : NEGF;
        float v30 = __shfl_sync(0xffffffffu, A, 30);
        if (lane == 31) {
            if (w < 16) { a30s[w * 1024] = v30; a31s[w * 1024] = A; }
            progC[w] = 0;
        }
        __syncthreads();   // publish t=0 boundaries + flags, then barrier-free

        int cached = 0;
        const int len = in_len[b];

        float gq[4];
#pragma unroll
        for (int k = 0; k < 4; k++) {
            int tt = 1 + k;
            gq[k] = (tt < NT) ? __ldg(lpb + (size_t)tt * NV + ext) : 0.f;
        }

        for (int t0 = 1; t0 < len; t0 += 4) {
            float gn[4];
#pragma unroll
            for (int k = 0; k < 4; k++) {
                int tt = t0 + 4 + k;
                gn[k] = (tt < NT) ? __ldg(lpb + (size_t)tt * NV + ext) : 0.f;
            }
#pragma unroll
            for (int k = 0; k < 4; k++) {
                const int t = t0 + k;
                if (t < len) {                       // uniform per block
                    float a2 = __shfl_up_sync(0xffffffffu, A, 1);
                    float a3 = __shfl_up_sync(0xffffffffu, A, 2);
                    if (lane < 2) {
                        if (w == 0) {
                            if (lane == 0) a2 = NEGF;
                            a3 = NEGF;
                        } else {
                            int need = t - 1;
                            while (cached < need) cached = acqLoad(&progC[w - 1]);
                            float b31 = a31s[(w - 1) * 1024 + need];
                            if (lane == 0) { a2 = b31; a3 = a30s[(w - 1) * 1024 + need]; }
                            else a3 = b31;
                        }
                    }
                    a3 = skip ? a3 : NEGF;
                    float mn, md, mx;
                    sort3(A, a2, a3, mn, md, mx);
                    float sum = 1.f + __expf(mn - mx) + __expf(md - mx);
                    A = mx + __logf(sum) + gq[k];
                    float w30 = __shfl_sync(0xffffffffu, A, 30);
                    if (lane == 31 && w < 16) {
                        a30s[w * 1024 + t] = w30;
                        a31s[w * 1024 + t] = A;
                        relStore(&progC[w], t);
                    }
                }
            }
#pragma unroll
            for (int k = 0; k < 4; k++) gq[k] = gn[k];
        }

        __syncthreads();
        if (tid <= 512) actc[tid] = A;
        __syncthreads();
        if (tid == 0) {
            int tl = tg_len[b];
            float aL = actc[2 * tl];
            float aP = actc[2 * tl - 1];
            float m = fmaxf(aL, aP);
            float ll = m + __logf(__expf(aL - m) + __expf(aP - m));
            g_loss[b] = -ll / (float)tl;
        }
    }
}

// ----------------------------------------------------------------------------
// Kernel 4: final reduction to scalar
// ----------------------------------------------------------------------------
__global__ void reduce_kernel(float* __restrict__ out) {
    const int tid = threadIdx.x;      // 128
    float v = g_loss[tid];
#pragma unroll
    for (int o = 16; o > 0; o >>= 1) v += __shfl_down_sync(0xffffffffu, v, o);
    __shared__ float ws[4];
    if ((tid & 31) == 0) ws[tid >> 5] = v;
    __syncthreads();
    if (tid == 0) out[0] = (ws[0] + ws[1] + ws[2] + ws[3]) * (1.f / (float)NB);
}

extern "C" void kernel_launch(void* const* d_in, const int* in_sizes, int n_in,
                              void* d_out, int out_size) {
    const float* lp  = (const float*)d_in[0];  // (B,T,V) f32
    const float* fm  = (const float*)d_in[1];  // (V,D)   f32
    const int*   tgt = (const int*)  d_in[2];  // (B,S)   i32
    const int*   il  = (const int*)  d_in[3];  // (B,)    i32
    const int*   tl  = (const int*)  d_in[4];  // (B,)    i32
    float* out = (float*)d_out;

    const int dynSmem = 2 * 17 * 1024 * 4 + 128 + (NL + 8) * 4;   // ~141.6 KB (CTC side max)
    cudaFuncSetAttribute(main_kernel, cudaFuncAttributeMaxDynamicSharedMemorySize, 150000);

    prep_kernel<<<512, 256>>>(lp, fm);
    cost_kernel<<<dim3(16, 64), 256>>>(fm, tgt);
    main_kernel<<<2 * NB, 544, dynSmem>>>(lp, tgt, il, tl);
    reduce_kernel<<<1, 128>>>(out);
}

// round 5
// speedup vs baseline: 1.4927x; 1.4927x over previous
#include <cuda_runtime.h>
#include <cstddef>
#include <cstdint>

#define NB 64
#define NT 1024
#define NV 256
#define NS 256
#define ND 24
#define NL 513          // 2*NS+1
#define DGA 1344        // allocated dg rows per batch
#define EMP 520         // padded emission row (513 -> 520)
#define NPH_S 87        // sdtw phases: 66 active + 3*7 lag
#define NPH_C 80        // ctc phases: 64 active + 16 lag
#define GAMMA 0.1f
#define NEGF (-1e10f)
#define BIGF (1e10f)

// Scratch (no allocation allowed)
__device__ float g_pred[NB * NT * ND];            // predicted features (B,T,D)
__device__ float g_cost[(size_t)NB * DGA * NS];   // cost, [b][dg][j], dg=i+j+2 (0-based i,j)
__device__ float g_em[(size_t)NB * NT * EMP];     // per-state emissions [b][t][s]
__device__ float g_loss[2 * NB];                  // [0..63] ctc, [64..127] sdtw

// mn <= md <= mx with pure min/max (no cancellation)
__device__ __forceinline__ void sort3(float a, float b, float c,
                                      float& mn, float& md, float& mx) {
    float t1 = fminf(a, b);
    float t2 = fmaxf(a, b);
    mn = fminf(t1, c);
    mx = fmaxf(t2, c);
    md = fmaxf(t1, fminf(t2, c));
}

// ----------------------------------------------------------------------------
// Kernel 1: pred = exp(log_probs) @ fm   (65536 x 256) @ (256 x 24)
// ----------------------------------------------------------------------------
__global__ __launch_bounds__(256) void prep_kernel(const float* __restrict__ lp,
                                                   const float* __restrict__ fm) {
    __shared__ float eS[64 * 129];
    __shared__ float fmS[64 * 25];

    const int tid = threadIdx.x;
    const int row0 = blockIdx.x * 128;
    const int rg = tid >> 3;
    const int dgrp = tid & 7;

    float acc[4][3];
#pragma unroll
    for (int i = 0; i < 4; i++)
#pragma unroll
        for (int j = 0; j < 3; j++) acc[i][j] = 0.f;

    for (int v0 = 0; v0 < NV; v0 += 64) {
        for (int idx = tid; idx < 64 * 24; idx += 256) {
            int v = idx / 24, d = idx - v * 24;
            fmS[v * 25 + d] = fm[(v0 + v) * ND + d];
        }
        for (int idx = tid; idx < 128 * 64; idx += 256) {
            int r = idx >> 6, v = idx & 63;
            eS[v * 129 + r] = __expf(lp[(size_t)(row0 + r) * NV + v0 + v]);
        }
        __syncthreads();

#pragma unroll 4
        for (int v = 0; v < 64; v++) {
            float e0 = eS[v * 129 + rg * 4 + 0];
            float e1 = eS[v * 129 + rg * 4 + 1];
            float e2 = eS[v * 129 + rg * 4 + 2];
            float e3 = eS[v * 129 + rg * 4 + 3];
            float f0 = fmS[v * 25 + dgrp * 3 + 0];
            float f1 = fmS[v * 25 + dgrp * 3 + 1];
            float f2 = fmS[v * 25 + dgrp * 3 + 2];
            acc[0][0] += e0 * f0; acc[0][1] += e0 * f1; acc[0][2] += e0 * f2;
            acc[1][0] += e1 * f0; acc[1][1] += e1 * f1; acc[1][2] += e1 * f2;
            acc[2][0] += e2 * f0; acc[2][1] += e2 * f1; acc[2][2] += e2 * f2;
            acc[3][0] += e3 * f0; acc[3][1] += e3 * f1; acc[3][2] += e3 * f2;
        }
        __syncthreads();
    }

#pragma unroll
    for (int i = 0; i < 4; i++)
#pragma unroll
        for (int j = 0; j < 3; j++)
            g_pred[(size_t)(row0 + rg * 4 + i) * ND + dgrp * 3 + j] = acc[i][j];
}

// ----------------------------------------------------------------------------
// Kernel 2: sdtw cost matrix, layout [b][dg][j], coalesced via diagonal rotation.
// ----------------------------------------------------------------------------
__global__ __launch_bounds__(256) void cost_kernel(const float* __restrict__ fm,
                                                   const int* __restrict__ targets) {
    __shared__ float predS[64 * 25];
    __shared__ float qS[256 * 25];
    __shared__ float pn[64];
    __shared__ float qn[256];
    __shared__ int qlab[256];

    const int tid = threadIdx.x;
    const int b = blockIdx.y;
    const int i0 = blockIdx.x * 64;

    qlab[tid] = targets[b * NS + tid];
    for (int idx = tid; idx < 64 * 24; idx += 256)
        predS[(idx / 24) * 25 + (idx % 24)] = g_pred[(size_t)(b * NT + i0) * ND + idx];
    __syncthreads();
    for (int idx = tid; idx < 256 * 24; idx += 256) {
        int c = idx / 24, d = idx - c * 24;
        qS[c * 25 + d] = fm[qlab[c] * ND + d];
    }
    __syncthreads();
    if (tid < 64) {
        float s = 0.f;
#pragma unroll
        for (int d = 0; d < ND; d++) { float x = predS[tid * 25 + d]; s += x * x; }
        pn[tid] = s;
    }
    {
        float s = 0.f;
#pragma unroll
        for (int d = 0; d < ND; d++) { float x = qS[tid * 25 + d]; s += x * x; }
        qn[tid] = s;
    }
    __syncthreads();

    const int w = tid >> 5;
    const int lane = tid & 31;
    const int j0 = w * 32;

    float p0[ND], p1[ND];
#pragma unroll
    for (int k = 0; k < ND; k++) {
        p0[k] = predS[lane * 25 + k];
        p1[k] = predS[(lane + 32) * 25 + k];
    }
    const float pn0 = pn[lane], pn1 = pn[lane + 32];
    const size_t cb = (size_t)b * DGA;
    const int D0 = i0 + j0 + 2;

#pragma unroll 4
    for (int c = 0; c < 32; c++) {
        int jc = j0 + ((c - lane) & 31);
        float dot0 = 0.f, dot1 = 0.f;
#pragma unroll
        for (int k = 0; k < ND; k++) {
            float q = qS[jc * 25 + k];
            dot0 += p0[k] * q;
            dot1 += p1[k] * q;
        }
        float qnj = qn[jc];
        int dg0 = D0 + c + ((lane > c) ? 32 : 0);
        g_cost[(cb + dg0) * NS + jc] = pn0 + qnj - 2.f * dot0;
        g_cost[(cb + dg0 + 32) * NS + jc] = pn1 + qnj - 2.f * dot1;
    }
}

// ----------------------------------------------------------------------------
// Kernel 3: per-state emission table EM[b][t][s]:
//   s even -> lp[b][t][0] (blank), s odd -> lp[b][t][label[(s-1)/2]].
// Block = (b, 64-t chunk), 256 threads; row staged in smem, gathers from smem.
// ----------------------------------------------------------------------------
__global__ __launch_bounds__(256) void em_kernel(const float* __restrict__ lp,
                                                 const int* __restrict__ targets) {
    __shared__ float rowS[256];
    __shared__ int extS[NL];

    const int tid = threadIdx.x;
    const int b = blockIdx.x >> 4;
    const int t0 = (blockIdx.x & 15) << 6;

    for (int s = tid; s < NL; s += 256)
        extS[s] = (s & 1) ? targets[b * NS + ((s - 1) >> 1)] : 0;
    const float* lpb = lp + ((size_t)b * NT + t0) * NV;
    float* emb = g_em + ((size_t)b * NT + t0) * EMP;
    __syncthreads();

    for (int tt = 0; tt < 64; tt++) {
        rowS[tid] = lpb[(size_t)tt * NV + tid];
        __syncthreads();
        float v0 = rowS[extS[tid]];
        float v1 = rowS[extS[tid + 256]];
        emb[(size_t)tt * EMP + tid] = v0;
        emb[(size_t)tt * EMP + tid + 256] = v1;
        if (tid == 0) emb[(size_t)tt * EMP + 512] = rowS[0];   // s=512 even -> blank
        __syncthreads();
    }
}

// ----------------------------------------------------------------------------
// Kernel 4 (fused DP, phase-skewed barriers — no polling):
//   blocks 0..63  -> soft-DTW : 8 warps, K=16 steps/phase, lag m=3
//   blocks 64..127-> CTC      : 17 warps, K=16 steps/phase, lag m=1
// Cross-warp boundary values via smem, ordered by the per-phase __syncthreads.
// ----------------------------------------------------------------------------
__global__ __launch_bounds__(544) void main_kernel(const int* __restrict__ targets,
                                                   const int* __restrict__ in_len,
                                                   const int* __restrict__ tg_len) {
    __shared__ float bndR[8][1280];      // sdtw: lane31 history, index dg-2
    __shared__ float ringA[17][32];      // ctc: lane30 vals, slot t&31
    __shared__ float ringB[17][32];      // ctc: lane31 vals
    __shared__ float actc[NL];

    const int tid = threadIdx.x;
    const int lane = tid & 31;
    const int w = tid >> 5;
    const int bid = blockIdx.x;

    if (bid < NB) {
        // ======================= soft-DTW =======================
        if (w >= 8) return;              // before any barrier
        const int b = bid;
        const int jj = tid + 1;          // column 1..256
        const int s0 = 32 * w + 2;       // first diagonal for this warp
        const float* cb = g_cost + (size_t)b * DGA * NS + tid;

        float Rp = BIGF;
        float r3c = (tid == 0) ? 0.f : BIGF;
        float buf0[16], buf1[16];
#pragma unroll
        for (int k = 0; k < 16; k++) {
            buf0[k] = cb[(size_t)(s0 + k) * NS];
            buf1[k] = cb[(size_t)(s0 + 16 + k) * NS];
        }

        auto phase = [&](float (&bufc)[16], int stBase) {
#pragma unroll
            for (int k = 0; k < 16; k++) {
                const int dg = s0 + stBase + k;
                float c = bufc[k];
                bufc[k] = cb[(size_t)(dg + 32) * NS];     // prefetch 2 phases ahead
                float r2 = __shfl_up_sync(0xffffffffu, Rp, 1);
                if (lane == 0)
                    r2 = (w == 0) ? BIGF : bndR[w - 1][dg - 3];
                float mn, md, mx;
                sort3(Rp, r2, r3c, mn, md, mx);
                float sexp = 1.f + __expf((mn - md) * 10.f) + __expf((mn - mx) * 10.f);
                const int i = dg - jj;
                float Rc = (i >= 1 && i <= NT) ? (c + mn - GAMMA * __logf(sexp)) : BIGF;
                if (lane == 31) bndR[w][dg - 2] = Rc;
                if (dg == NT + NS && tid == NS - 1) g_loss[NB + b] = Rc;
                r3c = r2;
                Rp = Rc;
            }
        };

        int cur = 0;
        for (int p = 0; p < NPH_S; p++) {
            const int stBase = (p - 3 * w) * 16;
            if (stBase >= 0 && stBase < 1056) {
                if (cur == 0) phase(buf0, stBase); else phase(buf1, stBase);
                cur ^= 1;
            }
            __syncthreads();
        }
    } else {
        // ======================= CTC forward =======================
        const int b = bid - NB;
        const int sC = (tid < NL) ? tid : (NL - 1);
        bool skip = false;
        if (sC & 1) {
            int kk = (sC - 1) >> 1;
            int e = targets[b * NS + kk];
            if (sC >= 3) skip = (e != targets[b * NS + kk - 1]);
        }
        const float* em = g_em + (size_t)b * NT * EMP + sC;
        const int len = in_len[b];

        // t = 0
        float A = (tid < 2) ? em[0] : NEGF;
        if (lane == 30) ringA[w][0] = A;
        if (lane == 31) ringB[w][0] = A;

        float buf0[16], buf1[16];
#pragma unroll
        for (int k = 0; k < 16; k++) {
            buf0[k] = em[(size_t)(1 + k) * EMP];
            buf1[k] = em[(size_t)(17 + k) * EMP];
        }

        auto phase = [&](float (&bufc)[16], int tBase) {
#pragma unroll
            for (int k = 0; k < 16; k++) {
                const int t = tBase + k;
                float e = bufc[k];
                int tp = t + 32; if (tp > NT - 1) tp = NT - 1;
                bufc[k] = em[(size_t)tp * EMP];           // prefetch 2 phases ahead
                if (t < len) {
                    float a2 = __shfl_up_sync(0xffffffffu, A, 1);
                    float a3 = __shfl_up_sync(0xffffffffu, A, 2);
                    if (lane < 2) {
                        if (w == 0) {
                            if (lane == 0) a2 = NEGF;
                            a3 = NEGF;
                        } else {
                            int slot = (t - 1) & 31;
                            float b31 = ringB[w - 1][slot];
                            if (lane == 0) { a2 = b31; a3 = ringA[w - 1][slot]; }
                            else a3 = b31;
                        }
                    }
                    a3 = skip ? a3 : NEGF;
                    float mn, md, mx;
                    sort3(A, a2, a3, mn, md, mx);
                    A = mx + __logf(1.f + __expf(mn - mx) + __expf(md - mx)) + e;
                    if (lane == 30) ringA[w][t & 31] = A;
                    if (lane == 31) ringB[w][t & 31] = A;
                }
            }
        };

        int cur = 0;
        for (int p = 0; p < NPH_C; p++) {
            const int tBase = 1 + (p - w) * 16;
            if (tBase >= 1 && tBase < NT) {
                if (cur == 0) phase(buf0, tBase); else phase(buf1, tBase);
                cur ^= 1;
            }
            __syncthreads();
        }

        if (tid < NL) actc[tid] = A;
        __syncthreads();
        if (tid == 0) {
            int tl = tg_len[b];
            float aL = actc[2 * tl];
            float aP = actc[2 * tl - 1];
            float m = fmaxf(aL, aP);
            float ll = m + __logf(__expf(aL - m) + __expf(aP - m));
            g_loss[b] = -ll / (float)tl;
        }
    }
}

// ----------------------------------------------------------------------------
// Kernel 5: final reduction to scalar
// ----------------------------------------------------------------------------
__global__ void reduce_kernel(float* __restrict__ out) {
    const int tid = threadIdx.x;      // 128
    float v = g_loss[tid];
#pragma unroll
    for (int o = 16; o > 0; o >>= 1) v += __shfl_down_sync(0xffffffffu, v, o);
    __shared__ float ws[4];
    if ((tid & 31) == 0) ws[tid >> 5] = v;
    __syncthreads();
    if (tid == 0) out[0] = (ws[0] + ws[1] + ws[2] + ws[3]) * (1.f / (float)NB);
}

extern "C" void kernel_launch(void* const* d_in, const int* in_sizes, int n_in,
                              void* d_out, int out_size) {
    const float* lp  = (const float*)d_in[0];  // (B,T,V) f32
    const float* fm  = (const float*)d_in[1];  // (V,D)   f32
    const int*   tgt = (const int*)  d_in[2];  // (B,S)   i32
    const int*   il  = (const int*)  d_in[3];  // (B,)    i32
    const int*   tl  = (const int*)  d_in[4];  // (B,)    i32
    float* out = (float*)d_out;

    prep_kernel<<<512, 256>>>(lp, fm);
    em_kernel<<<1024, 256>>>(lp, tgt);
    cost_kernel<<<dim3(16, 64), 256>>>(fm, tgt);
    main_kernel<<<2 * NB, 544>>>(tgt, il, tl);
    reduce_kernel<<<1, 128>>>(out);
}